// round 12
// baseline (speedup 1.0000x reference)
#include <cuda_runtime.h>
#include <math.h>
#include <stdint.h>

#define BB 8
#define NN 2500
#define EE 100
#define FF 50
#define YY 8922
#define KK 9
#define BY (BB*YY)

#define HS   52         // g_h row stride (208B, 16B-aligned)
#define ATY  256        // one y per thread
#define CN   448        // n rows per TMA chunk
#define NCHK 6          // 5*448 + 260
#define CHUNK_FLTS (CN*HS)   // 23296

typedef unsigned long long ull;

__device__ float g_h[BB*NN*HS];
__device__ float g_wT[900*52];
__device__ float g_invd[BY];
__device__ float g_loss[BY];

__device__ __forceinline__ void ffma2(ull &d, ull a, ull b) {
    asm("fma.rn.f32x2 %0, %1, %2, %0;" : "+l"(d) : "l"(a), "l"(b));
}
__device__ __forceinline__ ull pk2(float v) {
    ull r; unsigned u = __float_as_uint(v);
    asm("mov.b64 %0, {%1, %2};" : "=l"(r) : "r"(u), "r"(u));
    return r;
}
__device__ __forceinline__ float lo32(ull v){ return __uint_as_float((unsigned)v); }
__device__ __forceinline__ float hi32(ull v){ return __uint_as_float((unsigned)(v>>32)); }
__device__ __forceinline__ float sum2(ull v){ return lo32(v) + hi32(v); }

__device__ __forceinline__ uint32_t s2u(const void* p) {
    return (uint32_t)__cvta_generic_to_shared(p);
}
__device__ __forceinline__ void mbar_init(uint32_t mbar, int cnt) {
    asm volatile("mbarrier.init.shared.b64 [%0], %1;" :: "r"(mbar), "r"(cnt) : "memory");
}
__device__ __forceinline__ void tma_bulk(uint32_t dst, const void* src, uint32_t bytes, uint32_t mbar) {
    asm volatile("mbarrier.arrive.expect_tx.shared.b64 _, [%0], %1;" :: "r"(mbar), "r"(bytes) : "memory");
    asm volatile("cp.async.bulk.shared::cta.global.mbarrier::complete_tx::bytes [%0], [%1], %2, [%3];"
                 :: "r"(dst), "l"(src), "r"(bytes), "r"(mbar) : "memory");
}
__device__ __forceinline__ void mbar_wait(uint32_t mbar, int parity) {
    uint32_t done;
    do {
        asm volatile("{\n\t.reg .pred p;\n\t"
                     "mbarrier.try_wait.parity.acquire.cta.shared::cta.b64 p, [%1], %2, 0x989680;\n\t"
                     "selp.b32 %0, 1, 0, p;\n\t}"
                     : "=r"(done) : "r"(mbar), "r"((uint32_t)parity) : "memory");
    } while (!done);
}

// ======================= Kernel 0: transpose conv weights =======================
__global__ void wT_kernel(const float* __restrict__ convW) {
    int j = blockIdx.x*1024 + threadIdx.x;
    if (j < FF*EE*KK) {
        int f = j / 900, r = j - f*900;
        g_wT[r*52 + f] = convW[j];
    }
}

// ======================= Kernel 1: embed + conv1d(K=9,SAME) + tanh =======================
#define CVN 96
__global__ __launch_bounds__(384, 1)
void conv_kernel(const int* __restrict__ x, const float* __restrict__ embW,
                 const float* __restrict__ convB) {
    extern __shared__ float sm[];
    ull*   mbar = (ull*)sm;
    float* emb  = sm + 4;               // 104*101
    float* wsm  = emb + 104*101;        // 900*52
    int*   toks = (int*)(wsm + 900*52);

    int b = blockIdx.y, base = blockIdx.x * CVN, tid = threadIdx.x;
    uint32_t mb = s2u(&mbar[0]);

    if (tid < CVN + 8) {
        int n = base - 4 + tid;
        toks[tid] = (n >= 0 && n < NN) ? x[b*NN + n] : -1;
    }
    if (tid == 0) mbar_init(mb, 1);
    __syncthreads();
    if (tid == 0) tma_bulk(s2u(wsm), g_wT, 900*52*4, mb);

    for (int j = tid; j < (CVN+8)*EE; j += 384) {
        int row = j / EE, c = j - row*EE;
        int tk = toks[row];
        emb[row*101 + c] = (tk >= 0) ? embW[(size_t)tk*EE + c] : 0.f;
    }
    __syncthreads();
    mbar_wait(mb, 0);

    int tn = tid % CVN;
    int eq = tid / CVN;

    ull acc[25];
    #pragma unroll
    for (int q = 0; q < 25; q++) acc[q] = 0ull;

    for (int ee = 0; ee < 25; ee++) {
        int e = eq*25 + ee;
        #pragma unroll
        for (int k = 0; k < KK; k++) {
            ull v = pk2(emb[(tn + k)*101 + e]);
            const float* wr = &wsm[(e*KK + k)*52];
            #pragma unroll 4
            for (int i = 0; i < 12; i++) {
                ulonglong2 w2 = *(const ulonglong2*)(wr + 4*i);
                ffma2(acc[2*i],   w2.x, v);
                ffma2(acc[2*i+1], w2.y, v);
            }
            ffma2(acc[24], *(const ull*)(wr + 48), v);
        }
    }
    __syncthreads();
    float* part = sm + 4;
    if (eq > 0) {
        float* p = part + (eq-1)*CVN*FF + tn*FF;
        #pragma unroll
        for (int q = 0; q < 25; q++) {
            p[2*q]   = lo32(acc[q]);
            p[2*q+1] = hi32(acc[q]);
        }
    }
    __syncthreads();
    if (eq == 0) {
        int n = base + tn;
        if (n < NN) {
            float* dst = &g_h[((size_t)b*NN + n)*HS];
            const float* p0 = part + tn*FF;
            const float* p1 = part + CVN*FF + tn*FF;
            const float* p2 = part + 2*CVN*FF + tn*FF;
            #pragma unroll
            for (int q = 0; q < 25; q++) {
                float a0 = lo32(acc[q]) + p0[2*q]   + p1[2*q]   + p2[2*q]   + convB[2*q];
                float a1 = hi32(acc[q]) + p0[2*q+1] + p1[2*q+1] + p2[2*q+1] + convB[2*q+1];
                dst[2*q]   = tanhf(a0);
                dst[2*q+1] = tanhf(a1);
            }
        }
    }
}

// ======================= Kernel 2: thread-owns-y single-pass attention =======================
// grid (35, 8), 256 threads. Thread owns y = y0+tid; U row + F row in REGISTERS.
// Per n: s=U.h (broadcast LDS), t=F.h, e=exp(s); d+=e; lg+=e*t; e -> smem tile -> coalesced STG.
// No cross-thread reductions: logit = lg/d per thread. alpha normalized by norm_kernel.
__global__ __launch_bounds__(ATY, 1)
void attn_kernel(const float* __restrict__ Uw, const float* __restrict__ finW,
                 const float* __restrict__ finB, const float* __restrict__ tgt,
                 float* __restrict__ yhat_out, float* __restrict__ alpha_out) {
    extern __shared__ float sm[];
    ull*   mbar = (ull*)sm;              // 16B
    float* hbuf = sm + 4;                // 2*CHUNK_FLTS = 46592
    float* tile = hbuf + 2*CHUNK_FLTS;   // 256*33 = 8448

    int b = blockIdx.y, y0 = blockIdx.x*ATY, tid = threadIdx.x;
    int w = tid >> 5, lane = tid & 31;
    int y = y0 + tid;
    bool vy = (y < YY);
    int yc = vy ? y : (YY-1);
    const float* hb = g_h + (size_t)b*NN*HS;
    uint32_t mb0 = s2u(&mbar[0]), mb1 = s2u(&mbar[1]);

    if (tid == 0) { mbar_init(mb0, 1); mbar_init(mb1, 1); }

    // U and F rows into registers (one-time LDG)
    ull Ur[25], Fr[25];
    {
        const ull* us = (const ull*)(Uw  + (size_t)yc*FF);
        const ull* fs = (const ull*)(finW + (size_t)yc*FF);
        #pragma unroll
        for (int q = 0; q < 25; q++) { Ur[q] = us[q]; Fr[q] = fs[q]; }
    }
    __syncthreads();

    int ph0 = 0, ph1 = 0;
    if (tid == 0) tma_bulk(s2u(hbuf), hb, (uint32_t)(CN*HS*4), mb0);

    float d = 0.f, lg = 0.f;

    #pragma unroll 1
    for (int c = 0; c < NCHK; c++) {
        int slot = c & 1;
        if (c + 1 < NCHK && tid == 0) {
            uint32_t bytes = (c + 1 < NCHK - 1) ? (uint32_t)(CN*HS*4)
                                                : (uint32_t)((NN - (NCHK-1)*CN)*HS*4);
            tma_bulk(s2u(hbuf + ((c+1)&1)*CHUNK_FLTS), hb + (size_t)(c+1)*CN*HS, bytes,
                     slot ? mb0 : mb1);
        }
        if (slot == 0) { mbar_wait(mb0, ph0); ph0 ^= 1; }
        else           { mbar_wait(mb1, ph1); ph1 ^= 1; }
        const float* hc = hbuf + slot*CHUNK_FLTS;

        int rows = (c < NCHK-1) ? CN : (NN - (NCHK-1)*CN);
        int nblocks = (rows + 31) >> 5;

        #pragma unroll 1
        for (int blk = 0; blk < nblocks; blk++) {
            int w32 = rows - blk*32; if (w32 > 32) w32 = 32;

            #pragma unroll 1
            for (int nl = 0; nl < w32; nl++) {
                const ull* hr = (const ull*)(hc + (blk*32 + nl)*HS);  // broadcast
                ull s0 = 0ull, s1 = 0ull, t0 = 0ull, t1 = 0ull;      // dual chains
                #pragma unroll
                for (int q = 0; q < 24; q += 2) {
                    ull h0 = hr[q], h1 = hr[q+1];
                    ffma2(s0, Ur[q],   h0);
                    ffma2(s1, Ur[q+1], h1);
                    ffma2(t0, Fr[q],   h0);
                    ffma2(t1, Fr[q+1], h1);
                }
                {
                    ull h0 = hr[24];
                    ffma2(s0, Ur[24], h0);
                    ffma2(t0, Fr[24], h0);
                }
                float e = __expf(sum2(s0) + sum2(s1));
                d  += e;
                lg += e * (sum2(t0) + sum2(t1));
                tile[tid*33 + nl] = e;
            }
            __syncwarp();
            // cooperative coalesced store of this warp's 32 y-rows
            int nbase = c*CN + blk*32;
            #pragma unroll 4
            for (int r = 0; r < 32; r++) {
                int yr = y0 + w*32 + r;
                if (yr < YY && lane < w32)
                    alpha_out[(size_t)(b*YY + yr)*NN + nbase + lane] = tile[(w*32 + r)*33 + lane];
            }
            __syncwarp();
        }
        __syncthreads();   // all warps done with this buffer slot
    }

    // ---- per-thread epilogue: no reductions ----
    if (vy) {
        float iv = 1.f / d;
        g_invd[(size_t)b*YY + y] = iv;
        float logit = lg * iv + finB[y];
        float p = 1.f / (1.f + __expf(-logit));
        yhat_out[(size_t)b*YY + y] = p;
        float pc = fminf(fmaxf(p, 1e-7f), 1.f - 1e-7f);
        float t = tgt[(size_t)b*YY + y];
        g_loss[(size_t)b*YY + y] = -(t*logf(pc) + (1.f - t)*log1pf(-pc));
    }
}

// ======================= Kernel 3: alpha normalization (DRAM roofline) =======================
__global__ __launch_bounds__(256)
void norm_kernel(float* __restrict__ alpha) {
    size_t row = blockIdx.x;
    float inv = g_invd[row];
    float* p = alpha + row*NN;
    int t = threadIdx.x;
    #pragma unroll
    for (int i = 0; i < 10; i++) {
        int idx = t + i*256;
        if (idx < NN) p[idx] *= inv;
    }
}

// ======================= Kernel 4: deterministic loss reduction =======================
__global__ void loss_kernel(float* __restrict__ out) {
    __shared__ float r[1024];
    int tid = threadIdx.x;
    float a = 0.f;
    for (int i = tid; i < BY; i += 1024) a += g_loss[i];
    r[tid] = a;
    __syncthreads();
    for (int st = 512; st > 0; st >>= 1) {
        if (tid < st) r[tid] += r[tid + st];
        __syncthreads();
    }
    if (tid == 0) out[BY] = r[0] / (float)BY;
}

// ======================= Launch =======================
extern "C" void kernel_launch(void* const* d_in, const int* in_sizes, int n_in,
                              void* d_out, int out_size) {
    const int*   x      = (const int*)d_in[0];
    const float* target = (const float*)d_in[1];
    const float* embW   = (const float*)d_in[2];
    const float* convW  = (const float*)d_in[3];
    const float* convB  = (const float*)d_in[4];
    const float* Uw     = (const float*)d_in[5];
    const float* finW   = (const float*)d_in[6];
    const float* finB   = (const float*)d_in[7];
    float* out = (float*)d_out;
    float* yhat  = out;            // [B,Y]
    float* alpha = out + BY + 1;   // [B,Y,N]; out[BY] = loss

    const int conv_smem = (4 + 104*101 + 900*52)*4 + 104*4;        // 229648
    const int attn_smem = (4 + 2*CHUNK_FLTS + ATY*33)*4;           // 220176

    cudaFuncSetAttribute(conv_kernel, cudaFuncAttributeMaxDynamicSharedMemorySize, conv_smem);
    cudaFuncSetAttribute(attn_kernel, cudaFuncAttributeMaxDynamicSharedMemorySize, attn_smem);

    wT_kernel<<<(FF*EE*KK + 1023)/1024, 1024>>>(convW);
    conv_kernel<<<dim3((NN + CVN - 1)/CVN, BB), 384, conv_smem>>>(x, embW, convB);
    attn_kernel<<<dim3((YY + ATY - 1)/ATY, BB), ATY, attn_smem>>>(Uw, finW, finB, target, yhat, alpha);
    norm_kernel<<<BY, 256>>>(alpha);
    loss_kernel<<<1, 1024>>>(out);
}